// round 16
// baseline (speedup 1.0000x reference)
#include <cuda_runtime.h>
#include <math.h>

#define H    1024
#define NA   128
#define OP   16
#define G    32
#define UPB  7            // hidden units per block
#define NB   147          // 147*7 = 1029 >= 1024; all co-resident (<=148 SMs)
#define NT   480          // 15 warps: 14 compute (2 per unit) + 1 head warp
#define NW   15
#define NREP 4            // h-vector replicas (spread L2 slices)

typedef unsigned long long ull;

#define QSCALE   327670.0f         // |w| < 0.1 -> |q| <= 32767
#define QINV     (1.0f / 327670.0f)
#define DEC_BIAS (-8421376.0f)     // -(8388608 + 32768)

#define LAYER_STRIDE (UPB * 2 * 4 * H)          // u16 elements per layer per block
#define SMEM_DYN     (2 * LAYER_STRIDE * 2)     // bytes: 229376

// ---------------- persistent device state (no allocations allowed) ----------------
// Step-versioned h buffers: every phase writes FRESH addresses -> plain L1-cached
// loads are coherence-safe (no stale copy can exist; L1 flushed per launch).
__device__ __align__(16) float g_hv[NA][2][2][NREP][H];   // 8 MB
__device__ float g_ctx_logits[OP];
__device__ float g_left_logits[G];
__device__ unsigned g_count;                      // barrier counter; 0 at launch start
__device__ __align__(128) unsigned g_bcast[8 * 32];  // 8 broadcast words, own lines
__device__ unsigned g_flags[160];                 // per-block epochs (final barrier)

// ---------------- packed f32x2 helpers -------------------------------------------
__device__ __forceinline__ void fma2(ull& a, ull b, ull c) {
    asm("fma.rn.f32x2 %0, %1, %2, %0;" : "+l"(a) : "l"(b), "l"(c));
}
__device__ __forceinline__ ull pack2(float x, float y) {
    ull v; asm("mov.b64 %0, {%1, %2};" : "=l"(v) : "f"(x), "f"(y)); return v;
}
__device__ __forceinline__ float2 unpack2(ull v) {
    float2 f; asm("mov.b64 {%0, %1}, %2;" : "=f"(f.x), "=f"(f.y) : "l"(v)); return f;
}
// exact biased-u16 pair -> f32x2 of original int16 values (PRMT splice, no cvt)
__device__ __forceinline__ ull dec2(unsigned w, unsigned magic, ull bias2) {
    unsigned lo, hi;
    asm("prmt.b32 %0, %1, %2, 0x7410;" : "=r"(lo) : "r"(w), "r"(magic));
    asm("prmt.b32 %0, %1, %2, 0x7432;" : "=r"(hi) : "r"(w), "r"(magic));
    ull v;
    asm("mov.b64 %0, {%1, %2};" : "=l"(v) : "r"(lo), "r"(hi));
    asm("add.rn.f32x2 %0, %0, %1;" : "+l"(v) : "l"(bias2));
    return v;
}

__device__ __forceinline__ float warp_reduce(float v) {
#pragma unroll
    for (int o = 16; o; o >>= 1) v += __shfl_xor_sync(0xffffffffu, v, o);
    return v;
}
__device__ __forceinline__ float dot4(float4 a, float4 b) {
    return a.x * b.x + a.y * b.y + a.z * b.z + a.w * b.w;
}

// fast transcendentals (MUFU-based; err ~1e-6, far below 8e-5 quantization floor)
__device__ __forceinline__ float sigf(float x) {
    return __fdividef(1.f, 1.f + __expf(-x));
}
__device__ __forceinline__ float tanhff(float x) {
    return 1.f - __fdividef(2.f, __expf(2.f * x) + 1.f);
}

// ---------------- hierarchical grid barrier --------------------------------------
// Arrival: 1 RED per block on g_count (single-address REDs are cheap).
// Detection: ONLY block 0 polls the counter (zero contention), then release-stores
// the barrier index to 8 broadcast lines; other blocks poll bid&7's line
// (<=19 pollers/line). Transitive release/acquire chain orders the h-data.
__device__ __forceinline__ void grid_barrier(unsigned k) {
    __syncthreads();
    if (threadIdx.x == 0) {
        asm volatile("red.release.gpu.global.add.u32 [%0], 1;"
                     :: "l"(&g_count) : "memory");
        if (blockIdx.x == 0) {
            const unsigned target = k * (unsigned)NB;
            unsigned v;
            do {
                asm volatile("ld.acquire.gpu.global.u32 %0, [%1];"
                             : "=r"(v) : "l"(&g_count) : "memory");
            } while ((int)(v - target) < 0);
#pragma unroll
            for (int i = 0; i < 8; ++i)
                asm volatile("st.release.gpu.global.u32 [%0], %1;"
                             :: "l"(&g_bcast[i * 32]), "r"(k) : "memory");
        } else {
            const unsigned* p = &g_bcast[(blockIdx.x & 7) * 32];
            unsigned v;
            do {
                asm volatile("ld.acquire.gpu.global.u32 %0, [%1];"
                             : "=r"(v) : "l"(p) : "memory");
            } while ((int)(v - k) < 0);
        }
    }
    __syncthreads();
}

// all-to-all flags barrier: used ONCE at kernel end to make the resets safe.
__device__ __forceinline__ void flags_barrier(unsigned target, int lane) {
    __syncthreads();
    if (threadIdx.x == 0)
        asm volatile("st.release.gpu.global.u32 [%0], %1;"
                     :: "l"(&g_flags[blockIdx.x]), "r"(target) : "memory");
    if (threadIdx.x < 32) {
        for (;;) {
            bool ok = true;
#pragma unroll
            for (int k = 0; k < 5; ++k) {
                int idx = k * 32 + lane;
                unsigned f;
                asm volatile("ld.acquire.gpu.global.u32 %0, [%1];"
                             : "=r"(f) : "l"(&g_flags[idx]) : "memory");
                ok &= (idx >= NB) | ((int)(f - target) >= 0);
            }
            if (__all_sync(0xffffffffu, ok)) break;
        }
    }
    __syncthreads();
}

// per-warp partial: 4 gate rows (u16, SMEM) . vec (fp32, global; L1-cacheable
// because vectors are step-versioned/fresh), 1024 cols.
__device__ __forceinline__ void lstm_partial(
    const unsigned short* wbase,            // SMEM: [4][1024] u16 rows
    const float* __restrict__ vec,          // global: 1024 floats (fresh lines)
    int lane, float p[4])
{
    const unsigned magic = 0x4B000000u;
    const ull bias2 = pack2(DEC_BIAS, DEC_BIAS);
    ull acc[4] = {0, 0, 0, 0};

#pragma unroll
    for (int k = 0; k < 4; ++k) {
        const int c16 = k * 32 + lane;                  // 16B chunk id (0..127)
        const float4* vp = (const float4*)vec + c16 * 2;
        float4 va = vp[0];                              // plain ld -> L1 MSHR dedup
        float4 vb = vp[1];
        ull v0 = pack2(va.x, va.y), v1 = pack2(va.z, va.w);
        ull v2 = pack2(vb.x, vb.y), v3 = pack2(vb.z, vb.w);
#pragma unroll
        for (int r = 0; r < 4; ++r) {
            uint4 w = ((const uint4*)(wbase + r * H))[c16];   // LDS.128
            fma2(acc[r], dec2(w.x, magic, bias2), v0);
            fma2(acc[r], dec2(w.y, magic, bias2), v1);
            fma2(acc[r], dec2(w.z, magic, bias2), v2);
            fma2(acc[r], dec2(w.w, magic, bias2), v3);
        }
    }
#pragma unroll
    for (int g = 0; g < 4; ++g) {
        float2 s = unpack2(acc[g]);
        p[g] = warp_reduce(s.x + s.y);
    }
}

// head row dot: fp32 weight row (global, streaming) . x (global, fresh lines)
__device__ __forceinline__ float head_dot(const float* __restrict__ w,
                                          const float* __restrict__ x, int lane) {
    const float4* wv = (const float4*)w;
    const float4* xv = (const float4*)x;
    float a = 0.f;
#pragma unroll
    for (int it = 0; it < 8; ++it) {
        int t = it * 32 + lane;
        a += dot4(__ldcs(wv + t), xv[t]);
    }
    return warp_reduce(a);
}

// warp-parallel log-softmax; accumulates into acc-warp registers (deterministic).
__device__ __forceinline__ void warp_softmax_acc(const float* __restrict__ logits,
                                                 int n, int chosen, int lane,
                                                 float& ent, float& lp) {
    float v = (lane < n) ? __ldcg(logits + lane) : -1e30f;
    float m = v;
#pragma unroll
    for (int o = 16; o; o >>= 1) m = fmaxf(m, __shfl_xor_sync(0xffffffffu, m, o));
    float e = (lane < n) ? __expf(v - m) : 0.f;
    float se = e;
#pragma unroll
    for (int o = 16; o; o >>= 1) se += __shfl_xor_sync(0xffffffffu, se, o);
    float lse = m + __logf(se);
    float ls = v - lse;
    float t = (lane < n) ? __expf(ls) * ls : 0.f;
#pragma unroll
    for (int o = 16; o; o >>= 1) t += __shfl_xor_sync(0xffffffffu, t, o);
    float lsc = __shfl_sync(0xffffffffu, ls, chosen);
    ent += -t;
    lp  += lsc;
}

// ---------------- the single persistent kernel ------------------------------------
__global__ void __launch_bounds__(NT, 1)
controller_kernel(const float* __restrict__ g_emb,
                  const float* __restrict__ W_ih, const float* __restrict__ W_hh,
                  const float* __restrict__ b_ih, const float* __restrict__ b_hh,
                  const float* __restrict__ ctx_W, const float* __restrict__ ctx_b,
                  const float* __restrict__ left_W, const float* __restrict__ left_b,
                  const int* __restrict__ config, const int* __restrict__ left_config,
                  float* __restrict__ out)
{
    extern __shared__ unsigned short w_s[];           // [2][UPB][2][4][H] u16
    __shared__ float s_part[NW][4];
    __shared__ int   s_cfg[NA], s_lcfg[NA];
    __shared__ unsigned s_base;

    const int tid  = threadIdx.x;
    const int lane = tid & 31;
    const int wid  = tid >> 5;                         // 0..14
    const int bid  = blockIdx.x;
    const int rep  = bid & (NREP - 1);                 // read replica
    const int u    = wid >> 1;                         // unit within block
    const int m    = wid & 1;                          // 0 = ih (x), 1 = hh (h)
    const int j    = bid * UPB + u;
    const bool active = (wid < 14) && (j < H);

    const bool leftw = (wid == 14) && ((bid & 3) == 0) && ((bid >> 2) < G);
    const int  leftr = bid >> 2;
    const bool ctxw  = (wid == 14) && ((bid & 7) == 0) && ((bid >> 3) < OP);
    const int  ctxr  = bid >> 3;
    const bool accW  = (bid == 1) && (wid == 14);      // acc = head warp of bid 1

    float ent = 0.f, lp = 0.f;                         // acc-warp registers

#define HVP(A, S, L) (&g_hv[(A)][(S)][(L)][rep][0])
#define HVW(A, S, L) (&g_hv[(A)][(S)][(L)][0][0])

    // ---------------- prologue: fill SMEM weights (quantize fp32 -> biased u16) ----
    if (tid == 0) s_base = g_flags[bid];               // epoch for the final barrier
    if (tid < NA) { s_cfg[tid] = config[tid]; s_lcfg[tid] = left_config[tid]; }

    for (int idx = tid; idx < 2 * UPB * 2 * 4 * (H / 4); idx += NT) {
        int col = (idx & 255) * 4;                 // 256 float4 per row
        int t   = idx >> 8;
        int r   = t & 3;  t >>= 2;
        int mm  = t & 1;  t >>= 1;
        int k   = t % UPB;
        int l   = t / UPB;
        int jj  = bid * UPB + k;
        if (jj < H) {
            const float* src = (mm ? W_hh : W_ih) +
                               (size_t)l * 4 * H * H + ((size_t)r * H + jj) * H + col;
            float4 v = __ldcs((const float4*)src);
            ushort4 q;
            q.x = (unsigned short)(__float2int_rn(v.x * QSCALE) + 32768);
            q.y = (unsigned short)(__float2int_rn(v.y * QSCALE) + 32768);
            q.z = (unsigned short)(__float2int_rn(v.z * QSCALE) + 32768);
            q.w = (unsigned short)(__float2int_rn(v.w * QSCALE) + 32768);
            *(ushort4*)(w_s + ((((size_t)l * UPB + k) * 2 + mm) * 4 + r) * H + col) = q;
        }
    }

    // per-finalize-thread bias registers + cell-state registers (block-private!)
    const int jt = bid * UPB + tid;                    // unit for finalize thread tid<UPB
    const bool jt_ok = (tid < UPB) && (jt < H);
    float bsr[8];
    float c0 = 0.f, c1 = 0.f;                          // cell states, layers 0/1
    if (jt_ok) {
#pragma unroll
        for (int l = 0; l < 2; ++l)
#pragma unroll
            for (int g = 0; g < 4; ++g)
                bsr[l * 4 + g] = b_ih[l * 4 * H + g * H + jt] + b_hh[l * 4 * H + g * H + jt];
    }
    __syncthreads();
    unsigned bar = 0;                                  // counter-barrier index

    const unsigned short* wb0 = w_s + ((size_t)u * 2 + m) * 4 * H;       // layer 0
    const unsigned short* wb1 = wb0 + LAYER_STRIDE;                      // layer 1

#define DO_PHASE(WB, XV, HV, ZERO_H, CREG, ZERO_C, HOUT, LIDX)                  \
    do {                                                                        \
        if (active) {                                                           \
            float prt[4];                                                       \
            if (m == 0)            lstm_partial((WB), (XV), lane, prt);         \
            else if (ZERO_H)       { prt[0]=prt[1]=prt[2]=prt[3]=0.f; }         \
            else                   lstm_partial((WB), (HV), lane, prt);         \
            if (lane == 0) { s_part[wid][0]=prt[0]; s_part[wid][1]=prt[1];      \
                             s_part[wid][2]=prt[2]; s_part[wid][3]=prt[3]; }    \
        }                                                                       \
        HEADCODE;                                                               \
        __syncthreads();                                                        \
        if (jt_ok) {                                                            \
            float zi = (s_part[2*tid][0]+s_part[2*tid+1][0])*QINV + bsr[(LIDX)*4+0]; \
            float zf = (s_part[2*tid][1]+s_part[2*tid+1][1])*QINV + bsr[(LIDX)*4+1]; \
            float zg = (s_part[2*tid][2]+s_part[2*tid+1][2])*QINV + bsr[(LIDX)*4+2]; \
            float zo = (s_part[2*tid][3]+s_part[2*tid+1][3])*QINV + bsr[(LIDX)*4+3]; \
            float ii = sigf(zi);                                                \
            float ff = sigf(zf);                                                \
            float gg = tanhff(zg);                                              \
            float oo = sigf(zo);                                                \
            float cn = ff*((ZERO_C)?0.f:(CREG)) + ii*gg;                        \
            (CREG) = cn;                                                        \
            float hn = oo*tanhff(cn);                                           \
            float* hb = (HOUT);                                                 \
            _Pragma("unroll")                                                   \
            for (int r = 0; r < NREP; ++r) __stcg(hb + r * H + jt, hn);         \
        }                                                                       \
        grid_barrier(++bar);                                                    \
    } while (0)

    for (int a = 0; a < NA; ++a) {
        const bool first = (a == 0);
        const int  prevgap = first ? 0 : (s_cfg[a - 1] == 1);
        const int  sel   = prevgap;                    // state branch taken last step
        const bool gap   = (s_cfg[a] == 1);            // run gap phases this step?

        // ---- PHASE A: substep 0, layer 0 ------------------------------------------
#define HEADCODE                                                                \
        if (!first) {                                                           \
            if (prevgap) {                                                      \
                if (leftw) {                                                    \
                    float d = head_dot(left_W + ((size_t)(a-1) * G + leftr) * H,\
                                       HVP(a-1, 1, 1), lane);                   \
                    if (lane == 0) __stcg(&g_left_logits[leftr],                \
                                          d + left_b[(a-1)*G + leftr]);         \
                }                                                               \
            } else {                                                            \
                if (ctxw) {                                                     \
                    float d = head_dot(ctx_W + ((size_t)(a-1) * OP + ctxr) * H, \
                                       HVP(a-1, 0, 1), lane);                   \
                    if (lane == 0) __stcg(&g_ctx_logits[ctxr],                  \
                                          d + ctx_b[(a-1)*OP + ctxr]);          \
                }                                                               \
            }                                                                   \
        }
        DO_PHASE(wb0, (first ? g_emb : HVP(a-1, sel, 1)), HVP(a-1, sel, 0), first,
                 c0, first, HVW(a, 0, 0), 0);
#undef HEADCODE

        // ---- PHASE B: substep 0, layer 1 ------------------------------------------
#define HEADCODE                                                                \
        if (!first && accW) {                                                   \
            if (prevgap) warp_softmax_acc(g_left_logits, G, s_lcfg[a-1], lane,  \
                                          ent, lp);                             \
            else         warp_softmax_acc(g_ctx_logits, OP, s_cfg[a-1], lane,   \
                                          ent, lp);                             \
        }
        DO_PHASE(wb1, HVP(a, 0, 0), HVP(a-1, sel, 1), first,
                 c1, first, HVW(a, 0, 1), 1);
#undef HEADCODE

        if (gap) {
            // ---- PHASE C: substep 1 (gap), layer 0; head warp: ctx dots(a) --------
#define HEADCODE                                                                \
            if (ctxw) {                                                         \
                float d = head_dot(ctx_W + ((size_t)a * OP + ctxr) * H,         \
                                   HVP(a, 0, 1), lane);                         \
                if (lane == 0) __stcg(&g_ctx_logits[ctxr],                      \
                                      d + ctx_b[a * OP + ctxr]);                \
            }
            DO_PHASE(wb0, HVP(a, 0, 1), HVP(a, 0, 0), false,
                     c0, false, HVW(a, 1, 0), 0);
#undef HEADCODE

            // ---- PHASE D: substep 1 (gap), layer 1; acc warp: ctx softmax(a) ------
#define HEADCODE                                                                \
            if (accW) warp_softmax_acc(g_ctx_logits, OP, s_cfg[a], lane, ent, lp)
            DO_PHASE(wb1, HVP(a, 1, 0), HVP(a, 0, 1), false,
                     c1, false, HVW(a, 1, 1), 1);
#undef HEADCODE
        }
        // if !gap: phases C/D are exact no-ops (mask mf == 0) -> skipped; c0/c1
        // registers untouched == where(m, new, old) semantics.
    }

    // ---- epilogue: pending head work for the final step ---------------------------
    {
        const int lastgap = (s_cfg[NA - 1] == 1);
        if (lastgap) {
            if (leftw) {
                float d = head_dot(left_W + ((size_t)(NA - 1) * G + leftr) * H,
                                   HVP(NA-1, 1, 1), lane);
                if (lane == 0) __stcg(&g_left_logits[leftr],
                                      d + left_b[(NA - 1) * G + leftr]);
            }
        } else {
            if (ctxw) {
                float d = head_dot(ctx_W + ((size_t)(NA - 1) * OP + ctxr) * H,
                                   HVP(NA-1, 0, 1), lane);
                if (lane == 0) __stcg(&g_ctx_logits[ctxr],
                                      d + ctx_b[(NA - 1) * OP + ctxr]);
            }
        }
        grid_barrier(++bar);
        if (accW) {
            if (lastgap) warp_softmax_acc(g_left_logits, G, s_lcfg[NA - 1], lane, ent, lp);
            else         warp_softmax_acc(g_ctx_logits, OP, s_cfg[NA - 1], lane, ent, lp);
            if (lane == 0) { out[0] = ent; out[1] = lp; }
        }
    }

    // ---- final: flags barrier, then reset counter + bcast for the next launch -----
    flags_barrier(s_base + 1, lane);
    if (bid == 0 && tid == 0) {
        asm volatile("st.global.u32 [%0], 0;" :: "l"(&g_count) : "memory");
#pragma unroll
        for (int i = 0; i < 8; ++i)
            asm volatile("st.global.u32 [%0], 0;" :: "l"(&g_bcast[i * 32]) : "memory");
    }
#undef DO_PHASE
#undef HVP
#undef HVW
}

extern "C" void kernel_launch(void* const* d_in, const int* in_sizes, int n_in,
                              void* d_out, int out_size) {
    (void)in_sizes; (void)n_in; (void)out_size;
    const float* g_emb_p    = (const float*)d_in[0];
    const float* W_ih_p     = (const float*)d_in[1];
    const float* W_hh_p     = (const float*)d_in[2];
    const float* b_ih_p     = (const float*)d_in[3];
    const float* b_hh_p     = (const float*)d_in[4];
    const float* ctx_W_p    = (const float*)d_in[5];
    const float* ctx_b_p    = (const float*)d_in[6];
    const float* left_W_p   = (const float*)d_in[7];
    const float* left_b_p   = (const float*)d_in[8];
    const int*   config_p   = (const int*)d_in[9];
    const int*   left_cfg_p = (const int*)d_in[10];
    float* out = (float*)d_out;

    static int smem_set = 0;
    if (!smem_set) {
        cudaFuncSetAttribute(controller_kernel,
                             cudaFuncAttributeMaxDynamicSharedMemorySize, SMEM_DYN);
        smem_set = 1;
    }

    controller_kernel<<<NB, NT, SMEM_DYN>>>(g_emb_p, W_ih_p, W_hh_p, b_ih_p, b_hh_p,
                                            ctx_W_p, ctx_b_p, left_W_p, left_b_p,
                                            config_p, left_cfg_p, out);
}

// round 17
// speedup vs baseline: 2.0314x; 2.0314x over previous
#include <cuda_runtime.h>
#include <math.h>

#define H    1024
#define NA   128
#define OP   16
#define G    32
#define UPB  7            // hidden units per block
#define NB   147          // 147*7 = 1029 >= 1024; all co-resident (<=148 SMs)
#define NT   480          // 15 warps: 14 compute (2 per unit) + 1 head warp
#define NW   15
#define NREP 4            // h-vector replicas (spread L2 slices)
#define ARR  (NB * UPB)   // arrivals per barrier (7 per block)

typedef unsigned long long ull;

#define QSCALE   327670.0f         // |w| < 0.1 -> |q| <= 32767
#define QINV     (1.0f / 327670.0f)
#define DEC_BIAS (-8421376.0f)     // -(8388608 + 32768)

#define LAYER_STRIDE (UPB * 2 * 4 * H)          // u16 elements per layer per block
#define SMEM_DYN     (2 * LAYER_STRIDE * 2)     // bytes: 229376

// ---------------- persistent device state (no allocations allowed) ----------------
// Step-versioned h buffers: every phase writes FRESH addresses -> plain L1-cached
// loads are coherence-safe (no stale copy can exist; L1 flushed per launch).
__device__ __align__(16) float g_hv[NA][2][2][NREP][H];   // 8 MB
__device__ float g_ctx_logits[OP];
__device__ float g_left_logits[G];
__device__ unsigned g_count;                      // barrier counter; 0 at launch start
__device__ unsigned g_flags[160];                 // per-block epochs (final barrier)

// ---------------- packed f32x2 helpers -------------------------------------------
__device__ __forceinline__ void fma2(ull& a, ull b, ull c) {
    asm("fma.rn.f32x2 %0, %1, %2, %0;" : "+l"(a) : "l"(b), "l"(c));
}
__device__ __forceinline__ ull pack2(float x, float y) {
    ull v; asm("mov.b64 %0, {%1, %2};" : "=l"(v) : "f"(x), "f"(y)); return v;
}
__device__ __forceinline__ float2 unpack2(ull v) {
    float2 f; asm("mov.b64 {%0, %1}, %2;" : "=f"(f.x), "=f"(f.y) : "l"(v)); return f;
}
// exact biased-u16 pair -> f32x2 of original int16 values (PRMT splice, no cvt)
__device__ __forceinline__ ull dec2(unsigned w, unsigned magic, ull bias2) {
    unsigned lo, hi;
    asm("prmt.b32 %0, %1, %2, 0x7410;" : "=r"(lo) : "r"(w), "r"(magic));
    asm("prmt.b32 %0, %1, %2, 0x7432;" : "=r"(hi) : "r"(w), "r"(magic));
    ull v;
    asm("mov.b64 %0, {%1, %2};" : "=l"(v) : "r"(lo), "r"(hi));
    asm("add.rn.f32x2 %0, %0, %1;" : "+l"(v) : "l"(bias2));
    return v;
}

__device__ __forceinline__ float warp_reduce(float v) {
#pragma unroll
    for (int o = 16; o; o >>= 1) v += __shfl_xor_sync(0xffffffffu, v, o);
    return v;
}
__device__ __forceinline__ float dot4(float4 a, float4 b) {
    return a.x * b.x + a.y * b.y + a.z * b.z + a.w * b.w;
}

// ---------------- decentralized-arrival grid barrier ------------------------------
// Arrival: each finalize thread (tid<UPB) RED-releases right after ITS OWN stores
// (no block rendezvous before arrival). Detection: thread 0 weak-polls (.cg), then
// one acquire confirm establishes the synchronizes-with edge; trailing syncthreads
// releases the block.
__device__ __forceinline__ void barrier_arrive() {
    asm volatile("red.release.gpu.global.add.u32 [%0], 1;"
                 :: "l"(&g_count) : "memory");
}
__device__ __forceinline__ void barrier_wait(unsigned k) {
    const unsigned target = k * (unsigned)ARR;
    unsigned v;
    do {
        asm volatile("ld.global.cg.u32 %0, [%1];"
                     : "=r"(v) : "l"(&g_count) : "memory");
    } while ((int)(v - target) < 0);
    do {
        asm volatile("ld.acquire.gpu.global.u32 %0, [%1];"
                     : "=r"(v) : "l"(&g_count) : "memory");
    } while ((int)(v - target) < 0);
}

// all-to-all flags barrier: used ONCE at kernel end to make the counter reset safe.
__device__ __forceinline__ void flags_barrier(unsigned target, int lane) {
    __syncthreads();
    if (threadIdx.x == 0)
        asm volatile("st.release.gpu.global.u32 [%0], %1;"
                     :: "l"(&g_flags[blockIdx.x]), "r"(target) : "memory");
    if (threadIdx.x < 32) {
        for (;;) {
            bool ok = true;
#pragma unroll
            for (int k = 0; k < 5; ++k) {
                int idx = k * 32 + lane;
                unsigned f;
                asm volatile("ld.acquire.gpu.global.u32 %0, [%1];"
                             : "=r"(f) : "l"(&g_flags[idx]) : "memory");
                ok &= (idx >= NB) | ((int)(f - target) >= 0);
            }
            if (__all_sync(0xffffffffu, ok)) break;
        }
    }
    __syncthreads();
}

// per-warp partial: 4 gate rows (u16, SMEM) . vec (fp32, global; L1-cacheable
// because vectors are step-versioned/fresh), 1024 cols.
__device__ __forceinline__ void lstm_partial(
    const unsigned short* wbase,            // SMEM: [4][1024] u16 rows
    const float* __restrict__ vec,          // global: 1024 floats (fresh lines)
    int lane, float p[4])
{
    const unsigned magic = 0x4B000000u;
    const ull bias2 = pack2(DEC_BIAS, DEC_BIAS);
    ull acc[4] = {0, 0, 0, 0};

#pragma unroll
    for (int k = 0; k < 4; ++k) {
        const int c16 = k * 32 + lane;                  // 16B chunk id (0..127)
        const float4* vp = (const float4*)vec + c16 * 2;
        float4 va = vp[0];                              // plain ld -> L1 MSHR dedup
        float4 vb = vp[1];
        ull v0 = pack2(va.x, va.y), v1 = pack2(va.z, va.w);
        ull v2 = pack2(vb.x, vb.y), v3 = pack2(vb.z, vb.w);
#pragma unroll
        for (int r = 0; r < 4; ++r) {
            uint4 w = ((const uint4*)(wbase + r * H))[c16];   // LDS.128
            fma2(acc[r], dec2(w.x, magic, bias2), v0);
            fma2(acc[r], dec2(w.y, magic, bias2), v1);
            fma2(acc[r], dec2(w.z, magic, bias2), v2);
            fma2(acc[r], dec2(w.w, magic, bias2), v3);
        }
    }
#pragma unroll
    for (int g = 0; g < 4; ++g) {
        float2 s = unpack2(acc[g]);
        p[g] = warp_reduce(s.x + s.y);
    }
}

// head row dot: fp32 weight row (global, streaming) . x (global, fresh lines)
__device__ __forceinline__ float head_dot(const float* __restrict__ w,
                                          const float* __restrict__ x, int lane) {
    const float4* wv = (const float4*)w;
    const float4* xv = (const float4*)x;
    float a = 0.f;
#pragma unroll
    for (int it = 0; it < 8; ++it) {
        int t = it * 32 + lane;
        a += dot4(__ldcs(wv + t), xv[t]);
    }
    return warp_reduce(a);
}

// warp-parallel log-softmax; accumulates into acc-warp registers (deterministic).
__device__ __forceinline__ void warp_softmax_acc(const float* __restrict__ logits,
                                                 int n, int chosen, int lane,
                                                 float& ent, float& lp) {
    float v = (lane < n) ? __ldcg(logits + lane) : -1e30f;
    float m = v;
#pragma unroll
    for (int o = 16; o; o >>= 1) m = fmaxf(m, __shfl_xor_sync(0xffffffffu, m, o));
    float e = (lane < n) ? expf(v - m) : 0.f;
    float se = e;
#pragma unroll
    for (int o = 16; o; o >>= 1) se += __shfl_xor_sync(0xffffffffu, se, o);
    float lse = m + logf(se);
    float ls = v - lse;
    float t = (lane < n) ? expf(ls) * ls : 0.f;
#pragma unroll
    for (int o = 16; o; o >>= 1) t += __shfl_xor_sync(0xffffffffu, t, o);
    float lsc = __shfl_sync(0xffffffffu, ls, chosen);
    ent += -t;
    lp  += lsc;
}

// ---------------- the single persistent kernel ------------------------------------
__global__ void __launch_bounds__(NT, 1)
controller_kernel(const float* __restrict__ g_emb,
                  const float* __restrict__ W_ih, const float* __restrict__ W_hh,
                  const float* __restrict__ b_ih, const float* __restrict__ b_hh,
                  const float* __restrict__ ctx_W, const float* __restrict__ ctx_b,
                  const float* __restrict__ left_W, const float* __restrict__ left_b,
                  const int* __restrict__ config, const int* __restrict__ left_config,
                  float* __restrict__ out)
{
    extern __shared__ unsigned short w_s[];           // [2][UPB][2][4][H] u16
    __shared__ float s_part[NW][4];
    __shared__ int   s_cfg[NA], s_lcfg[NA];
    __shared__ unsigned s_base;

    const int tid  = threadIdx.x;
    const int lane = tid & 31;
    const int wid  = tid >> 5;                         // 0..14
    const int bid  = blockIdx.x;
    const int rep  = bid & (NREP - 1);                 // read replica
    const int u    = wid >> 1;                         // unit within block
    const int m    = wid & 1;                          // 0 = ih (x), 1 = hh (h)
    const int j    = bid * UPB + u;
    const bool active = (wid < 14) && (j < H);

    const bool leftw = (wid == 14) && ((bid & 3) == 0) && ((bid >> 2) < G);
    const int  leftr = bid >> 2;
    const bool ctxw  = (wid == 14) && ((bid & 7) == 0) && ((bid >> 3) < OP);
    const int  ctxr  = bid >> 3;
    const bool accW  = (bid == 1) && (wid == 14);      // acc = head warp of bid 1

    float ent = 0.f, lp = 0.f;                         // acc-warp registers

#define HVP(A, S, L) (&g_hv[(A)][(S)][(L)][rep][0])
#define HVW(A, S, L) (&g_hv[(A)][(S)][(L)][0][0])

    // ---------------- prologue: fill SMEM weights (quantize fp32 -> biased u16) ----
    if (tid == 0) s_base = g_flags[bid];               // epoch for the final barrier
    if (tid < NA) { s_cfg[tid] = config[tid]; s_lcfg[tid] = left_config[tid]; }

    for (int idx = tid; idx < 2 * UPB * 2 * 4 * (H / 4); idx += NT) {
        int col = (idx & 255) * 4;                 // 256 float4 per row
        int t   = idx >> 8;
        int r   = t & 3;  t >>= 2;
        int mm  = t & 1;  t >>= 1;
        int k   = t % UPB;
        int l   = t / UPB;
        int jj  = bid * UPB + k;
        if (jj < H) {
            const float* src = (mm ? W_hh : W_ih) +
                               (size_t)l * 4 * H * H + ((size_t)r * H + jj) * H + col;
            float4 v = __ldcs((const float4*)src);
            ushort4 q;
            q.x = (unsigned short)(__float2int_rn(v.x * QSCALE) + 32768);
            q.y = (unsigned short)(__float2int_rn(v.y * QSCALE) + 32768);
            q.z = (unsigned short)(__float2int_rn(v.z * QSCALE) + 32768);
            q.w = (unsigned short)(__float2int_rn(v.w * QSCALE) + 32768);
            *(ushort4*)(w_s + ((((size_t)l * UPB + k) * 2 + mm) * 4 + r) * H + col) = q;
        }
    }

    // per-finalize-thread bias registers + cell-state registers (block-private!)
    const int jt = bid * UPB + tid;                    // unit for finalize thread tid<UPB
    const bool jt_ok = (tid < UPB) && (jt < H);
    float bsr[8];
    float c0 = 0.f, c1 = 0.f;                          // cell states, layers 0/1
    if (jt_ok) {
#pragma unroll
        for (int l = 0; l < 2; ++l)
#pragma unroll
            for (int g = 0; g < 4; ++g)
                bsr[l * 4 + g] = b_ih[l * 4 * H + g * H + jt] + b_hh[l * 4 * H + g * H + jt];
    }
    __syncthreads();
    unsigned bar = 0;                                  // counter-barrier index

    const unsigned short* wb0 = w_s + ((size_t)u * 2 + m) * 4 * H;       // layer 0
    const unsigned short* wb1 = wb0 + LAYER_STRIDE;                      // layer 1

#define DO_PHASE(WB, XV, HV, ZERO_H, CREG, ZERO_C, HOUT, LIDX)                  \
    do {                                                                        \
        if (active) {                                                           \
            float prt[4];                                                       \
            if (m == 0)            lstm_partial((WB), (XV), lane, prt);         \
            else if (ZERO_H)       { prt[0]=prt[1]=prt[2]=prt[3]=0.f; }         \
            else                   lstm_partial((WB), (HV), lane, prt);         \
            if (lane == 0) { s_part[wid][0]=prt[0]; s_part[wid][1]=prt[1];      \
                             s_part[wid][2]=prt[2]; s_part[wid][3]=prt[3]; }    \
        }                                                                       \
        HEADCODE;                                                               \
        __syncthreads();                                                        \
        ++bar;                                                                  \
        if (tid < UPB) {                                                        \
            if (jt_ok) {                                                        \
                float zi = (s_part[2*tid][0]+s_part[2*tid+1][0])*QINV + bsr[(LIDX)*4+0]; \
                float zf = (s_part[2*tid][1]+s_part[2*tid+1][1])*QINV + bsr[(LIDX)*4+1]; \
                float zg = (s_part[2*tid][2]+s_part[2*tid+1][2])*QINV + bsr[(LIDX)*4+2]; \
                float zo = (s_part[2*tid][3]+s_part[2*tid+1][3])*QINV + bsr[(LIDX)*4+3]; \
                float ii = 1.f/(1.f+expf(-zi));                                 \
                float ff = 1.f/(1.f+expf(-zf));                                 \
                float gg = tanhf(zg);                                           \
                float oo = 1.f/(1.f+expf(-zo));                                 \
                float cn = ff*((ZERO_C)?0.f:(CREG)) + ii*gg;                    \
                (CREG) = cn;                                                    \
                float hn = oo*tanhf(cn);                                        \
                float* hb = (HOUT);                                             \
                _Pragma("unroll")                                               \
                for (int r = 0; r < NREP; ++r) __stcg(hb + r * H + jt, hn);     \
            }                                                                   \
            barrier_arrive();                          /* releases own stores */ \
            if (tid == 0) barrier_wait(bar);                                    \
        }                                                                       \
        __syncthreads();                                                        \
    } while (0)

    for (int a = 0; a < NA; ++a) {
        const bool first = (a == 0);
        const int  prevgap = first ? 0 : (s_cfg[a - 1] == 1);
        const int  sel   = prevgap;                    // state branch taken last step
        const bool gap   = (s_cfg[a] == 1);            // run gap phases this step?

        // ---- PHASE A: substep 0, layer 0 ------------------------------------------
#define HEADCODE                                                                \
        if (!first) {                                                           \
            if (prevgap) {                                                      \
                if (leftw) {                                                    \
                    float d = head_dot(left_W + ((size_t)(a-1) * G + leftr) * H,\
                                       HVP(a-1, 1, 1), lane);                   \
                    if (lane == 0) __stcg(&g_left_logits[leftr],                \
                                          d + left_b[(a-1)*G + leftr]);         \
                }                                                               \
            } else {                                                            \
                if (ctxw) {                                                     \
                    float d = head_dot(ctx_W + ((size_t)(a-1) * OP + ctxr) * H, \
                                       HVP(a-1, 0, 1), lane);                   \
                    if (lane == 0) __stcg(&g_ctx_logits[ctxr],                  \
                                          d + ctx_b[(a-1)*OP + ctxr]);          \
                }                                                               \
            }                                                                   \
        }
        DO_PHASE(wb0, (first ? g_emb : HVP(a-1, sel, 1)), HVP(a-1, sel, 0), first,
                 c0, first, HVW(a, 0, 0), 0);
#undef HEADCODE

        // ---- PHASE B: substep 0, layer 1 ------------------------------------------
#define HEADCODE                                                                \
        if (!first && accW) {                                                   \
            if (prevgap) warp_softmax_acc(g_left_logits, G, s_lcfg[a-1], lane,  \
                                          ent, lp);                             \
            else         warp_softmax_acc(g_ctx_logits, OP, s_cfg[a-1], lane,   \
                                          ent, lp);                             \
        }
        DO_PHASE(wb1, HVP(a, 0, 0), HVP(a-1, sel, 1), first,
                 c1, first, HVW(a, 0, 1), 1);
#undef HEADCODE

        if (gap) {
            // ---- PHASE C: substep 1 (gap), layer 0; head warp: ctx dots(a) --------
#define HEADCODE                                                                \
            if (ctxw) {                                                         \
                float d = head_dot(ctx_W + ((size_t)a * OP + ctxr) * H,         \
                                   HVP(a, 0, 1), lane);                         \
                if (lane == 0) __stcg(&g_ctx_logits[ctxr],                      \
                                      d + ctx_b[a * OP + ctxr]);                \
            }
            DO_PHASE(wb0, HVP(a, 0, 1), HVP(a, 0, 0), false,
                     c0, false, HVW(a, 1, 0), 0);
#undef HEADCODE

            // ---- PHASE D: substep 1 (gap), layer 1; acc warp: ctx softmax(a) ------
#define HEADCODE                                                                \
            if (accW) warp_softmax_acc(g_ctx_logits, OP, s_cfg[a], lane, ent, lp)
            DO_PHASE(wb1, HVP(a, 1, 0), HVP(a, 0, 1), false,
                     c1, false, HVW(a, 1, 1), 1);
#undef HEADCODE
        }
        // if !gap: phases C/D are exact no-ops (mask mf == 0) -> skipped; c0/c1
        // registers untouched == where(m, new, old) semantics.
    }

    // ---- epilogue: pending head work for the final step ---------------------------
    {
        const int lastgap = (s_cfg[NA - 1] == 1);
        if (lastgap) {
            if (leftw) {
                float d = head_dot(left_W + ((size_t)(NA - 1) * G + leftr) * H,
                                   HVP(NA-1, 1, 1), lane);
                if (lane == 0) __stcg(&g_left_logits[leftr],
                                      d + left_b[(NA - 1) * G + leftr]);
            }
        } else {
            if (ctxw) {
                float d = head_dot(ctx_W + ((size_t)(NA - 1) * OP + ctxr) * H,
                                   HVP(NA-1, 0, 1), lane);
                if (lane == 0) __stcg(&g_ctx_logits[ctxr],
                                      d + ctx_b[(NA - 1) * OP + ctxr]);
            }
        }
        __syncthreads();                      // head stores ordered before arrivals
        ++bar;
        if (tid < UPB) {
            barrier_arrive();
            if (tid == 0) barrier_wait(bar);
        }
        __syncthreads();
        if (accW) {
            if (lastgap) warp_softmax_acc(g_left_logits, G, s_lcfg[NA - 1], lane, ent, lp);
            else         warp_softmax_acc(g_ctx_logits, OP, s_cfg[NA - 1], lane, ent, lp);
            if (lane == 0) { out[0] = ent; out[1] = lp; }
        }
    }

    // ---- final: flags barrier, then reset the counter for the next launch ---------
    flags_barrier(s_base + 1, lane);
    if (bid == 0 && tid == 0)
        asm volatile("st.global.u32 [%0], 0;" :: "l"(&g_count) : "memory");
#undef DO_PHASE
#undef HVP
#undef HVW
}

extern "C" void kernel_launch(void* const* d_in, const int* in_sizes, int n_in,
                              void* d_out, int out_size) {
    (void)in_sizes; (void)n_in; (void)out_size;
    const float* g_emb_p    = (const float*)d_in[0];
    const float* W_ih_p     = (const float*)d_in[1];
    const float* W_hh_p     = (const float*)d_in[2];
    const float* b_ih_p     = (const float*)d_in[3];
    const float* b_hh_p     = (const float*)d_in[4];
    const float* ctx_W_p    = (const float*)d_in[5];
    const float* ctx_b_p    = (const float*)d_in[6];
    const float* left_W_p   = (const float*)d_in[7];
    const float* left_b_p   = (const float*)d_in[8];
    const int*   config_p   = (const int*)d_in[9];
    const int*   left_cfg_p = (const int*)d_in[10];
    float* out = (float*)d_out;

    static int smem_set = 0;
    if (!smem_set) {
        cudaFuncSetAttribute(controller_kernel,
                             cudaFuncAttributeMaxDynamicSharedMemorySize, SMEM_DYN);
        smem_set = 1;
    }

    controller_kernel<<<NB, NT, SMEM_DYN>>>(g_emb_p, W_ih_p, W_hh_p, b_ih_p, b_hh_p,
                                            ctx_W_p, ctx_b_p, left_W_p, left_b_p,
                                            config_p, left_cfg_p, out);
}